// round 5
// baseline (speedup 1.0000x reference)
#include <cuda_runtime.h>

#define NSIDE    48
#define NPIX     2304          // 48*48
#define NTHREADS 576           // 48 rows x 12 col-groups (4 cols each)
#define NWARPS   18
#define INV_EPS  100.0f
#define MAXB     64

__device__ float g_cost[MAXB];
__device__ unsigned int g_count = 0;

__device__ __forceinline__ float4 ld4(const float* p) {
    return *reinterpret_cast<const float4*>(p);
}
__device__ __forceinline__ void st4(float* p, float4 v) {
    *reinterpret_cast<float4*>(p) = v;
}
__device__ __forceinline__ float mass_of(float x) {
    return fminf(fmaxf(x, 0.0f), 1e9f) + 1e-9f;
}

// ---------------------------------------------------------------------------
// block reduce (all threads receive the sum; deterministic order)
// ---------------------------------------------------------------------------
__device__ __forceinline__ float block_reduce(float val, float* red) {
#pragma unroll
    for (int o = 16; o; o >>= 1) val += __shfl_down_sync(0xffffffffu, val, o);
    if ((threadIdx.x & 31) == 0) red[threadIdx.x >> 5] = val;
    __syncthreads();
    float s = red[0];
#pragma unroll
    for (int w = 1; w < NWARPS; w++) s += red[w];
    __syncthreads();   // red reusable after return
    return s;
}

// ---------------------------------------------------------------------------
// One output row-slice of a dense 48x48 matmul: returns (A*B)[r, c0..c0+3].
// A row element is a warp-broadcast scalar LDS; B is a float4 LDS.
// ---------------------------------------------------------------------------
__device__ __forceinline__ float4 mm_row(const float* __restrict__ A,
                                         const float* __restrict__ B,
                                         int r, int c0) {
    float4 acc = make_float4(0.f, 0.f, 0.f, 0.f);
    const float* arow = A + r * NSIDE;
#pragma unroll
    for (int b = 0; b < NSIDE; b++) {
        float av  = arow[b];
        float4 bv = ld4(B + b * NSIDE + c0);
        acc.x = fmaf(av, bv.x, acc.x);
        acc.y = fmaf(av, bv.y, acc.y);
        acc.z = fmaf(av, bv.z, acc.z);
        acc.w = fmaf(av, bv.w, acc.w);
    }
    return acc;
}

// ---------------------------------------------------------------------------
// One CTA per batch image. Sinkhorn in the multiplicative (scaling) domain:
//   a = e^{u/eps}, b = e^{v/eps};  update a <- mu*a/(a*(K b K) + 1e-6), etc.
// This is algebraically identical to the reference's log-domain update with
// the non-shifted lse and its +1e-6.
// ---------------------------------------------------------------------------
__global__ __launch_bounds__(NTHREADS)
void sinkhorn_kernel(const float* __restrict__ y, const float* __restrict__ yt,
                     float* __restrict__ out, int nb) {
    __shared__ __align__(16) float sK [NPIX];  // exp(-d^2/eps), separable Gibbs
    __shared__ __align__(16) float sKD[NPIX];  // K * d^2
    __shared__ __align__(16) float sA [NPIX];  // a = e^{u/eps}
    __shared__ __align__(16) float sB [NPIX];  // b = e^{v/eps}
    __shared__ __align__(16) float sT [NPIX];  // matmul temp
    __shared__ float red[NWARPS];

    const int tid = threadIdx.x;
    const int r   = tid / 12;          // output row 0..47
    const int c0  = (tid % 12) * 4;    // output col block
    const int idx = r * NSIDE + c0;

    const float* yb  = y  + (size_t)blockIdx.x * NPIX;
    const float* ytb = yt + (size_t)blockIdx.x * NPIX;

    // Build dense K and KD matrices (grid spacing 1/48, p=2 cost, eps=0.01)
    for (int i = tid; i < NPIX; i += NTHREADS) {
        int row = i / NSIDE, col = i % NSIDE;
        int d  = row - col; d = d < 0 ? -d : d;
        float dd = (float)d * (1.0f / 48.0f);
        float d2 = dd * dd;
        float k  = expf(-d2 * INV_EPS);
        sK[i]  = k;
        sKD[i] = k * d2;
    }

    // mass sums
    float sxl = 0.0f, syl = 0.0f;
    for (int i = tid; i < NPIX; i += NTHREADS) {
        sxl += mass_of(yb[i]);
        syl += mass_of(ytb[i]);
    }
    __syncthreads();
    const float sx = block_reduce(sxl, red);
    const float sy = block_reduce(syl, red);

    // per-thread mu/nu and scalings (registers)
    float4 yv  = ld4(yb  + idx);
    float4 ytv = ld4(ytb + idx);
    float4 mu4 = make_float4(mass_of(yv.x)  / sx, mass_of(yv.y)  / sx,
                             mass_of(yv.z)  / sx, mass_of(yv.w)  / sx);
    float4 nu4 = make_float4(mass_of(ytv.x) / sy, mass_of(ytv.y) / sy,
                             mass_of(ytv.z) / sy, mass_of(ytv.w) / sy);
    float4 a4 = make_float4(1.f, 1.f, 1.f, 1.f);
    float4 b4 = make_float4(1.f, 1.f, 1.f, 1.f);
    st4(&sA[idx], a4);
    st4(&sB[idx], b4);
    __syncthreads();   // sK/sKD/sA/sB ready

    // 5 Sinkhorn iterations
#pragma unroll 1
    for (int it = 0; it < 5; it++) {
        // u-update: S = K * B * K ; a <- mu*a/(a*S + 1e-6)
        float4 t = mm_row(sK, sB, r, c0);
        st4(&sT[idx], t);
        __syncthreads();
        float4 s = mm_row(sT, sK, r, c0);
        a4.x = mu4.x * a4.x / (a4.x * s.x + 1e-6f);
        a4.y = mu4.y * a4.y / (a4.y * s.y + 1e-6f);
        a4.z = mu4.z * a4.z / (a4.z * s.z + 1e-6f);
        a4.w = mu4.w * a4.w / (a4.w * s.w + 1e-6f);
        st4(&sA[idx], a4);
        __syncthreads();

        // v-update: S = K * A * K ; b <- nu*b/(b*S + 1e-6)
        t = mm_row(sK, sA, r, c0);
        st4(&sT[idx], t);
        __syncthreads();
        s = mm_row(sT, sK, r, c0);
        b4.x = nu4.x * b4.x / (b4.x * s.x + 1e-6f);
        b4.y = nu4.y * b4.y / (b4.y * s.y + 1e-6f);
        b4.z = nu4.z * b4.z / (b4.z * s.z + 1e-6f);
        b4.w = nu4.w * b4.w / (b4.w * s.w + 1e-6f);
        st4(&sB[idx], b4);
        __syncthreads();
    }

    // cost = sum_i a_i * [ (KD B K) + (K B KD) ]_i   (separable C = Dy + Dx)
    float cl;
    {
        float4 t = mm_row(sKD, sB, r, c0);
        st4(&sT[idx], t);
        __syncthreads();
        float4 s = mm_row(sT, sK, r, c0);
        cl = a4.x * s.x + a4.y * s.y + a4.z * s.z + a4.w * s.w;
        __syncthreads();   // before overwriting sT

        t = mm_row(sK, sB, r, c0);
        st4(&sT[idx], t);
        __syncthreads();
        s = mm_row(sT, sKD, r, c0);
        cl += a4.x * s.x + a4.y * s.y + a4.z * s.z + a4.w * s.w;
    }

    float c = block_reduce(cl, red);

    // last CTA finalizes the batch mean (counter self-resets: replay-safe)
    if (tid == 0) {
        g_cost[blockIdx.x] = c;
        __threadfence();
        unsigned done = atomicAdd(&g_count, 1u);
        if (done == (unsigned)(nb - 1)) {
            float ssum = 0.0f;
            for (int i = 0; i < nb; i++) ssum += g_cost[i];
            *out = ssum / (float)nb;
            g_count = 0;
        }
    }
}

extern "C" void kernel_launch(void* const* d_in, const int* in_sizes, int n_in,
                              void* d_out, int out_size) {
    const float* y  = (const float*)d_in[0];
    const float* yt = (const float*)d_in[1];
    float* out = (float*)d_out;

    int nb = in_sizes[0] / NPIX;   // 16
    if (nb < 1)    nb = 1;
    if (nb > MAXB) nb = MAXB;

    sinkhorn_kernel<<<nb, NTHREADS>>>(y, yt, out, nb);
}

// round 6
// speedup vs baseline: 2.6078x; 2.6078x over previous
#include <cuda_runtime.h>

#define NSIDE    48
#define NPIX     2304          // 48*48
#define LDW      52            // padded smem row stride (floats): kills A-load bank conflicts
#define NTHREADS 288           // 24 row-groups(2 rows) x 12 col-groups(4 cols)
#define NWARPS   9
#define INV_EPS  100.0f
#define MAXB     64

__device__ float g_cost[MAXB];
__device__ unsigned int g_count = 0;

__device__ __forceinline__ float4 ld4(const float* p) {
    return *reinterpret_cast<const float4*>(p);
}
__device__ __forceinline__ void st4(float* p, float4 v) {
    *reinterpret_cast<float4*>(p) = v;
}
__device__ __forceinline__ float mass_of(float x) {
    return fminf(fmaxf(x, 0.0f), 1e9f) + 1e-9f;
}

// ---------------------------------------------------------------------------
// block reduce (all threads receive the sum; deterministic order)
// ---------------------------------------------------------------------------
__device__ __forceinline__ float block_reduce(float val, float* red) {
#pragma unroll
    for (int o = 16; o; o >>= 1) val += __shfl_down_sync(0xffffffffu, val, o);
    if ((threadIdx.x & 31) == 0) red[threadIdx.x >> 5] = val;
    __syncthreads();
    float s = red[0];
#pragma unroll
    for (int w = 1; w < NWARPS; w++) s += red[w];
    __syncthreads();   // red reusable after return
    return s;
}

// ---------------------------------------------------------------------------
// Dense 48x48 matmul slice: acc[i] = (A*B)[r0+i, c0..c0+3], i=0..1.
// A: scalar broadcast-ish loads (stride LDW=52 -> conflict-free across warp's
// row groups). B: one LDS.128 shared across both rows.
// ---------------------------------------------------------------------------
__device__ __forceinline__ void mm2x4(const float* __restrict__ A,
                                      const float* __restrict__ B,
                                      int r0, int c0, float4 acc[2]) {
    acc[0] = make_float4(0.f, 0.f, 0.f, 0.f);
    acc[1] = make_float4(0.f, 0.f, 0.f, 0.f);
    const float* a0p = A + r0 * LDW;
    const float* a1p = A + (r0 + 1) * LDW;
#pragma unroll 16
    for (int b = 0; b < NSIDE; b++) {
        float  a0 = a0p[b];
        float  a1 = a1p[b];
        float4 bv = ld4(B + b * LDW + c0);
        acc[0].x = fmaf(a0, bv.x, acc[0].x);
        acc[0].y = fmaf(a0, bv.y, acc[0].y);
        acc[0].z = fmaf(a0, bv.z, acc[0].z);
        acc[0].w = fmaf(a0, bv.w, acc[0].w);
        acc[1].x = fmaf(a1, bv.x, acc[1].x);
        acc[1].y = fmaf(a1, bv.y, acc[1].y);
        acc[1].z = fmaf(a1, bv.z, acc[1].z);
        acc[1].w = fmaf(a1, bv.w, acc[1].w);
    }
}

// ---------------------------------------------------------------------------
// One CTA per batch image. Sinkhorn in the multiplicative (scaling) domain:
//   a = e^{u/eps}, b = e^{v/eps};  a <- mu*a/(a*(K b K) + 1e-6), etc.
// Exactly matches the reference's log-domain update with non-shifted lse +1e-6.
// ---------------------------------------------------------------------------
__global__ __launch_bounds__(NTHREADS)
void sinkhorn_kernel(const float* __restrict__ y, const float* __restrict__ yt,
                     float* __restrict__ out, int nb) {
    __shared__ __align__(16) float sK[NSIDE * LDW];   // dense Gibbs kernel
    __shared__ __align__(16) float sA[NSIDE * LDW];   // a (also temp in cost)
    __shared__ __align__(16) float sB[NSIDE * LDW];   // b
    __shared__ __align__(16) float sT[NSIDE * LDW];   // matmul temp
    __shared__ float ktab[NSIDE];
    __shared__ float kdtab[NSIDE];
    __shared__ float red[NWARPS];

    const int tid = threadIdx.x;
    const int r0  = (tid / 12) * 2;    // rows r0, r0+1
    const int c0  = (tid % 12) * 4;    // col block

    const float* yb  = y  + (size_t)blockIdx.x * NPIX;
    const float* ytb = yt + (size_t)blockIdx.x * NPIX;

    // |d| tables and dense K (grid spacing 1/48, p=2 cost, eps=0.01)
    if (tid < NSIDE) {
        float dd = (float)tid * (1.0f / 48.0f);
        float d2 = dd * dd;
        float k  = expf(-d2 * INV_EPS);
        ktab[tid]  = k;
        kdtab[tid] = k * d2;
    }
    for (int i = tid; i < NPIX; i += NTHREADS) {
        int ro = i / NSIDE, co = i % NSIDE;
        int d  = ro - co; d = d < 0 ? -d : d;
        float dd = (float)d * (1.0f / 48.0f);
        sK[ro * LDW + co] = expf(-dd * dd * INV_EPS);
    }

    // mass sums
    float sxl = 0.0f, syl = 0.0f;
    for (int i = tid; i < NPIX; i += NTHREADS) {
        sxl += mass_of(yb[i]);
        syl += mass_of(ytb[i]);
    }
    __syncthreads();
    const float sx = block_reduce(sxl, red);
    const float sy = block_reduce(syl, red);
    const float rsx = 1.0f / sx, rsy = 1.0f / sy;

    // per-thread mu/nu and scalings (registers), init a=b=1
    float4 mu4[2], nu4[2], a4[2], b4[2];
#pragma unroll
    for (int i = 0; i < 2; i++) {
        int gidx = (r0 + i) * NSIDE + c0;
        float4 yv  = ld4(yb  + gidx);
        float4 ytv = ld4(ytb + gidx);
        mu4[i] = make_float4(mass_of(yv.x) * rsx, mass_of(yv.y) * rsx,
                             mass_of(yv.z) * rsx, mass_of(yv.w) * rsx);
        nu4[i] = make_float4(mass_of(ytv.x) * rsy, mass_of(ytv.y) * rsy,
                             mass_of(ytv.z) * rsy, mass_of(ytv.w) * rsy);
        a4[i] = make_float4(1.f, 1.f, 1.f, 1.f);
        b4[i] = make_float4(1.f, 1.f, 1.f, 1.f);
        st4(&sA[(r0 + i) * LDW + c0], a4[i]);
        st4(&sB[(r0 + i) * LDW + c0], b4[i]);
    }
    __syncthreads();

    // 5 Sinkhorn iterations
    float4 t[2], s[2];
#pragma unroll 1
    for (int it = 0; it < 5; it++) {
        // u-update: S = K*B*K ; a <- mu*a / (a*S + 1e-6)
        mm2x4(sK, sB, r0, c0, t);
        st4(&sT[r0 * LDW + c0], t[0]);
        st4(&sT[(r0 + 1) * LDW + c0], t[1]);
        __syncthreads();
        mm2x4(sT, sK, r0, c0, s);
#pragma unroll
        for (int i = 0; i < 2; i++) {
            a4[i].x = __fdividef(mu4[i].x * a4[i].x, fmaf(a4[i].x, s[i].x, 1e-6f));
            a4[i].y = __fdividef(mu4[i].y * a4[i].y, fmaf(a4[i].y, s[i].y, 1e-6f));
            a4[i].z = __fdividef(mu4[i].z * a4[i].z, fmaf(a4[i].z, s[i].z, 1e-6f));
            a4[i].w = __fdividef(mu4[i].w * a4[i].w, fmaf(a4[i].w, s[i].w, 1e-6f));
            st4(&sA[(r0 + i) * LDW + c0], a4[i]);
        }
        __syncthreads();

        // v-update: S = K*A*K ; b <- nu*b / (b*S + 1e-6)
        mm2x4(sK, sA, r0, c0, t);
        st4(&sT[r0 * LDW + c0], t[0]);
        st4(&sT[(r0 + 1) * LDW + c0], t[1]);
        __syncthreads();
        mm2x4(sT, sK, r0, c0, s);
#pragma unroll
        for (int i = 0; i < 2; i++) {
            b4[i].x = __fdividef(nu4[i].x * b4[i].x, fmaf(b4[i].x, s[i].x, 1e-6f));
            b4[i].y = __fdividef(nu4[i].y * b4[i].y, fmaf(b4[i].y, s[i].y, 1e-6f));
            b4[i].z = __fdividef(nu4[i].z * b4[i].z, fmaf(b4[i].z, s[i].z, 1e-6f));
            b4[i].w = __fdividef(nu4[i].w * b4[i].w, fmaf(b4[i].w, s[i].w, 1e-6f));
            st4(&sB[(r0 + i) * LDW + c0], b4[i]);
        }
        __syncthreads();
    }

    // cost = sum_i a_i * [ (KD*B*K) + (K*B*KD) ]_i  — fused into 2 passes.
    // Pass 1: T1 = KD*B (-> sT), T2 = K*B (-> sA; a lives in registers now).
    {
        float4 t1[2], t2[2];
        t1[0] = t1[1] = t2[0] = t2[1] = make_float4(0.f, 0.f, 0.f, 0.f);
#pragma unroll 16
        for (int b = 0; b < NSIDE; b++) {
            int d0 = r0 - b;     d0 = d0 < 0 ? -d0 : d0;
            int d1 = r0 + 1 - b; d1 = d1 < 0 ? -d1 : d1;
            float kd0 = kdtab[d0], kd1 = kdtab[d1];
            float k0  = ktab[d0],  k1  = ktab[d1];
            float4 bv = ld4(sB + b * LDW + c0);
            t1[0].x = fmaf(kd0, bv.x, t1[0].x); t1[0].y = fmaf(kd0, bv.y, t1[0].y);
            t1[0].z = fmaf(kd0, bv.z, t1[0].z); t1[0].w = fmaf(kd0, bv.w, t1[0].w);
            t1[1].x = fmaf(kd1, bv.x, t1[1].x); t1[1].y = fmaf(kd1, bv.y, t1[1].y);
            t1[1].z = fmaf(kd1, bv.z, t1[1].z); t1[1].w = fmaf(kd1, bv.w, t1[1].w);
            t2[0].x = fmaf(k0, bv.x, t2[0].x);  t2[0].y = fmaf(k0, bv.y, t2[0].y);
            t2[0].z = fmaf(k0, bv.z, t2[0].z);  t2[0].w = fmaf(k0, bv.w, t2[0].w);
            t2[1].x = fmaf(k1, bv.x, t2[1].x);  t2[1].y = fmaf(k1, bv.y, t2[1].y);
            t2[1].z = fmaf(k1, bv.z, t2[1].z);  t2[1].w = fmaf(k1, bv.w, t2[1].w);
        }
        __syncthreads();   // everyone done reading sB/old sA before overwrite
        st4(&sT[r0 * LDW + c0], t1[0]);
        st4(&sT[(r0 + 1) * LDW + c0], t1[1]);
        st4(&sA[r0 * LDW + c0], t2[0]);
        st4(&sA[(r0 + 1) * LDW + c0], t2[1]);
        __syncthreads();
    }

    // Pass 2: S1 = T1*K, S2 = T2*KD; cl = sum a .* (S1 + S2)
    float cl = 0.0f;
    {
        float4 s1[2], s2[2];
        s1[0] = s1[1] = s2[0] = s2[1] = make_float4(0.f, 0.f, 0.f, 0.f);
        const float* t1p0 = sT + r0 * LDW;
        const float* t1p1 = sT + (r0 + 1) * LDW;
        const float* t2p0 = sA + r0 * LDW;
        const float* t2p1 = sA + (r0 + 1) * LDW;
#pragma unroll 16
        for (int b = 0; b < NSIDE; b++) {
            float p0 = t1p0[b], p1 = t1p1[b];
            float q0 = t2p0[b], q1 = t2p1[b];
            float4 kv = ld4(sK + b * LDW + c0);
            int e0 = b - c0;     e0 = e0 < 0 ? -e0 : e0;
            int e1 = b - c0 - 1; e1 = e1 < 0 ? -e1 : e1;
            int e2 = b - c0 - 2; e2 = e2 < 0 ? -e2 : e2;
            int e3 = b - c0 - 3; e3 = e3 < 0 ? -e3 : e3;
            float kd0 = kdtab[e0], kd1 = kdtab[e1], kd2 = kdtab[e2], kd3 = kdtab[e3];
            s1[0].x = fmaf(p0, kv.x, s1[0].x); s1[0].y = fmaf(p0, kv.y, s1[0].y);
            s1[0].z = fmaf(p0, kv.z, s1[0].z); s1[0].w = fmaf(p0, kv.w, s1[0].w);
            s1[1].x = fmaf(p1, kv.x, s1[1].x); s1[1].y = fmaf(p1, kv.y, s1[1].y);
            s1[1].z = fmaf(p1, kv.z, s1[1].z); s1[1].w = fmaf(p1, kv.w, s1[1].w);
            s2[0].x = fmaf(q0, kd0, s2[0].x);  s2[0].y = fmaf(q0, kd1, s2[0].y);
            s2[0].z = fmaf(q0, kd2, s2[0].z);  s2[0].w = fmaf(q0, kd3, s2[0].w);
            s2[1].x = fmaf(q1, kd0, s2[1].x);  s2[1].y = fmaf(q1, kd1, s2[1].y);
            s2[1].z = fmaf(q1, kd2, s2[1].z);  s2[1].w = fmaf(q1, kd3, s2[1].w);
        }
#pragma unroll
        for (int i = 0; i < 2; i++) {
            cl += a4[i].x * (s1[i].x + s2[i].x);
            cl += a4[i].y * (s1[i].y + s2[i].y);
            cl += a4[i].z * (s1[i].z + s2[i].z);
            cl += a4[i].w * (s1[i].w + s2[i].w);
        }
    }

    float c = block_reduce(cl, red);

    // last CTA finalizes the batch mean (counter self-resets: replay-safe)
    if (tid == 0) {
        g_cost[blockIdx.x] = c;
        __threadfence();
        unsigned done = atomicAdd(&g_count, 1u);
        if (done == (unsigned)(nb - 1)) {
            float ssum = 0.0f;
            for (int i = 0; i < nb; i++) ssum += g_cost[i];
            *out = ssum / (float)nb;
            g_count = 0;
        }
    }
}

extern "C" void kernel_launch(void* const* d_in, const int* in_sizes, int n_in,
                              void* d_out, int out_size) {
    const float* y  = (const float*)d_in[0];
    const float* yt = (const float*)d_in[1];
    float* out = (float*)d_out;

    int nb = in_sizes[0] / NPIX;   // 16
    if (nb < 1)    nb = 1;
    if (nb > MAXB) nb = MAXB;

    sinkhorn_kernel<<<nb, NTHREADS>>>(y, yt, out, nb);
}